// round 11
// baseline (speedup 1.0000x reference)
#include <cuda_runtime.h>
#include <cuda_fp16.h>
#include <cstdint>

#define B_TOT 8192
#define T_STEPS 90
#define H 128
#define NB 64
#define NCTA 128
#define NTHR 512
#define SKB 272u          // act row stride bytes (128 fp16 + 8 pad)
#define CSTRIDE 68        // c buffer row stride (floats)

// ---- SMEM byte offsets ----
#define OFF_XA    0u          // [64][136] fp16
#define OFF_H0    17408u
#define OFF_H1    34816u
#define OFF_SCR   52224u      // phase-A xproj [64][132] f32 / tail xhf [128][65] f32
#define OFF_C0    86016u      // [128][68] f32
#define OFF_C1    120832u
#define OFF_XROW  155648u     // [64][8] f32 (also LN scratch)
#define OFF_WIN   157696u     // [128][8] f32 (slot7 = b_in)
#define OFF_LNP   161792u     // g_in,be_in,g_ln,be_ln (4x128 f32)
#define OFF_B0    163840u
#define OFF_B1    165888u
#define SMEM_TOTAL 167936u
// tail overlays: d1o @0 (acts dead, 32KB), d2o @34816 (16KB)

// ---- device globals ----
// layout: [(L*8+w)][g][ks][hl][512B]  (strides 65536 / 16384 / 1024 / 512), fp16
__device__ __align__(256) uint8_t g_Wpack[1048576];
__device__ float g_Wd1t[128 * 128];
__device__ float g_Wd2t[128 * 64];
__device__ float g_bias0[512];
__device__ float g_bias1[512];

__global__ void prep_kernel(const float* __restrict__ Wih0, const float* __restrict__ Whh0,
                            const float* __restrict__ bih0, const float* __restrict__ bhh0,
                            const float* __restrict__ Wih1, const float* __restrict__ Whh1,
                            const float* __restrict__ bih1, const float* __restrict__ bhh1,
                            const float* __restrict__ Wd1,  const float* __restrict__ Wd2)
{
    int idx = blockIdx.x * blockDim.x + threadIdx.x;
    int stride = gridDim.x * blockDim.x;
    // mma m16n8k16 a-fragment order with fp16 hi/lo split
    for (int i = idx; i < 524288; i += stride) {
        int e    = i & 1;
        int reg  = (i >> 1) & 3;
        int lane = (i >> 3) & 31;
        int hl   = (i >> 8) & 1;
        int ks   = (i >> 9) & 15;
        int g    = (i >> 13) & 3;
        int w    = (i >> 15) & 7;
        int L    = (i >> 18) & 1;
        int j = g * 128 + w * 16 + (lane >> 2) + (reg & 1) * 8;
        int k = ks * 16 + (lane & 3) * 2 + ((reg >> 1) & 1) * 8 + e;
        float v;
        if (L == 0) v = (k < H) ? Wih0[j * H + k] : Whh0[j * H + (k - H)];
        else        v = (k < H) ? Wih1[j * H + k] : Whh1[j * H + (k - H)];
        __half hi = __float2half_rn(v);
        __half lo = __float2half_rn(v - __half2float(hi));
        reinterpret_cast<__half*>(g_Wpack)[i] = hl ? lo : hi;
    }
    for (int i = idx; i < 128 * 128; i += stride) {
        int k = i >> 7, d = i & 127;
        g_Wd1t[i] = Wd1[d * H + k];
    }
    for (int i = idx; i < 128 * 64; i += stride) {
        int k = i >> 6, d = i & 63;
        g_Wd2t[i] = Wd2[d * 128 + k];
    }
    for (int i = idx; i < 512; i += stride) {
        g_bias0[i] = bih0[i] + bhh0[i];
        g_bias1[i] = bih1[i] + bhh1[i];
    }
}

// ---- helpers ----
__device__ __forceinline__ uint32_t smem_u32_of(const void* p) {
    uint32_t a;
    asm("{ .reg .u64 t; cvta.to.shared.u64 t, %1; cvt.u32.u64 %0, t; }" : "=r"(a) : "l"(p));
    return a;
}
__device__ __forceinline__ void ldmx4(uint32_t& r0, uint32_t& r1, uint32_t& r2, uint32_t& r3,
                                      uint32_t addr) {
    asm volatile("ldmatrix.sync.aligned.m8n8.x4.shared.b16 {%0,%1,%2,%3}, [%4];"
                 : "=r"(r0), "=r"(r1), "=r"(r2), "=r"(r3) : "r"(addr));
}
__device__ __forceinline__ void mma16816(float* c, uint4 a, uint32_t b0, uint32_t b1) {
    asm volatile("mma.sync.aligned.m16n8k16.row.col.f32.f16.f16.f32 "
                 "{%0,%1,%2,%3}, {%4,%5,%6,%7}, {%8,%9}, {%0,%1,%2,%3};"
                 : "+f"(c[0]), "+f"(c[1]), "+f"(c[2]), "+f"(c[3])
                 : "r"(a.x), "r"(a.y), "r"(a.z), "r"(a.w), "r"(b0), "r"(b1));
}
__device__ __forceinline__ float sigf(float x) {
    return __fdividef(1.f, 1.f + __expf(-x));
}
__device__ __forceinline__ float tanh_fast(float x) {
    return 2.f * sigf(2.f * x) - 1.f;
}

__global__ void __launch_bounds__(NTHR, 1)
lstm_hmma_kernel(const float* __restrict__ x,
                 const float* __restrict__ W_in, const float* __restrict__ b_in,
                 const float* __restrict__ g_in, const float* __restrict__ be_in,
                 const float* __restrict__ g_ln, const float* __restrict__ be_ln,
                 const float* __restrict__ b_d1, const float* __restrict__ b_d2,
                 const float* __restrict__ W_d3, const float* __restrict__ b_d3,
                 float* __restrict__ out)
{
    extern __shared__ __align__(256) uint8_t smb[];
    const int tid   = threadIdx.x;
    const int w     = tid >> 5;
    const int wq    = w & 7;           // h-row group
    const int nhalf = w >> 3;          // n half (0: cols 0-31, 1: cols 32-63)
    const int lane  = tid & 31;
    const int bbase = blockIdx.x * NB;

    uint32_t smbase = smem_u32_of(smb);
    float* scr  = reinterpret_cast<float*>(smb + OFF_SCR);
    float* xrow = reinterpret_cast<float*>(smb + OFF_XROW);   // also LN scratch
    float* wins = reinterpret_cast<float*>(smb + OFF_WIN);
    float* lnp  = reinterpret_cast<float*>(smb + OFF_LNP);
    float* b0s  = reinterpret_cast<float*>(smb + OFF_B0);
    float* b1s  = reinterpret_cast<float*>(smb + OFF_B1);

    // ---- prologue ----
    for (int i = tid; i < (3 * 17408) / 4; i += NTHR)
        reinterpret_cast<uint32_t*>(smb + OFF_XA)[i] = 0u;            // act buffers
    for (int i = tid; i < 2 * 128 * CSTRIDE; i += NTHR)
        reinterpret_cast<float*>(smb + OFF_C0)[i] = 0.f;
    for (int i = tid; i < H * 7; i += NTHR) {
        int h = i / 7, f = i % 7;
        wins[h * 8 + f] = W_in[i];
    }
    for (int i = tid; i < H; i += NTHR) {
        wins[i * 8 + 7] = b_in[i];
        lnp[i] = g_in[i]; lnp[128 + i] = be_in[i];
        lnp[256 + i] = g_ln[i]; lnp[384 + i] = be_ln[i];
    }
    for (int i = tid; i < 512; i += NTHR) { b0s[i] = g_bias0[i]; b1s[i] = g_bias1[i]; }
    __syncthreads();

    // ldmatrix lane offset within a 16-row (2 n-tile) group
    const int tI = lane >> 3, r = lane & 7;
    const uint32_t loffb = (uint32_t)((tI >> 1) * 8 + r) * SKB + (uint32_t)(tI & 1) * 16u
                         + (uint32_t)nhalf * 32u * SKB;

    const int m0  = wq * 16 + (lane >> 2);     // h row (second row = +8)
    const int nb0 = (lane & 3) * 2;

    for (int t = 0; t < T_STEPS; ++t) {
        // ================= phase A: x -> proj -> LN -> fp16 xa =================
        if (tid < NB) {
            const float* xr = x + ((long long)(bbase + tid) * T_STEPS + t) * 7;
#pragma unroll
            for (int f = 0; f < 7; ++f) xrow[tid * 8 + f] = xr[f];
        }
        __syncthreads();
        {
            int b = tid >> 3, hq = tid & 7;
            float xv[7];
#pragma unroll
            for (int f = 0; f < 7; ++f) xv[f] = xrow[b * 8 + f];
            for (int h = hq * 16; h < hq * 16 + 16; ++h) {
                float s = wins[h * 8 + 7];
#pragma unroll
                for (int f = 0; f < 7; ++f) s += wins[h * 8 + f] * xv[f];
                scr[b * 132 + h] = s;
            }
        }
        __syncthreads();
        // LN: stage 1 partial sums
        if (tid < 128) {
            int b = tid >> 1, hf = tid & 1;
            float s = 0.f, ss = 0.f;
            for (int h = hf * 64; h < hf * 64 + 64; ++h) {
                float v = scr[b * 132 + h];
                s += v; ss += v * v;
            }
            xrow[b * 2 + hf] = s;
            xrow[128 + b * 2 + hf] = ss;
        }
        __syncthreads();
        if (tid < NB) {
            int b = tid;
            float s  = xrow[b * 2] + xrow[b * 2 + 1];
            float ss = xrow[128 + b * 2] + xrow[128 + b * 2 + 1];
            float mu = s * (1.f / H);
            float rs = rsqrtf(ss * (1.f / H) - mu * mu + 1e-5f);
            xrow[256 + b] = mu;
            xrow[320 + b] = rs;
        }
        __syncthreads();
        for (int i = tid; i < NB * H; i += NTHR) {
            int b = i >> 7, h = i & 127;
            float v = (scr[b * 132 + h] - xrow[256 + b]) * xrow[320 + b] * lnp[h] + lnp[128 + h];
            *reinterpret_cast<__half*>(smb + OFF_XA + (uint32_t)b * SKB + (uint32_t)h * 2u) =
                __float2half_rn(v);
        }
        __syncthreads();

        // ================= two LSTM layers =================
#pragma unroll 1
        for (int L = 0; L < 2; ++L) {
            const uint8_t* wbase = g_Wpack + (size_t)(L * 8 + wq) * 65536;
            uint32_t in_b  = smbase + (L == 0 ? OFF_XA : OFF_H0);
            uint32_t re_b  = smbase + (L == 0 ? OFF_H0 : OFF_H1);
            uint32_t out_b = (L == 0 ? OFF_H0 : OFF_H1);
            float* cbuf = reinterpret_cast<float*>(smb + (L == 0 ? OFF_C0 : OFF_C1));
            const float* bs = (L == 0) ? b0s : b1s;

            float acc[4][4][4];
#pragma unroll
            for (int g = 0; g < 4; ++g)
#pragma unroll
                for (int nt = 0; nt < 4; ++nt)
#pragma unroll
                    for (int q = 0; q < 4; ++q) acc[g][nt][q] = 0.f;

#pragma unroll 4
            for (int ks = 0; ks < 16; ++ks) {
                uint32_t bh_base = ((ks < 8) ? in_b : re_b) + (uint32_t)(ks & 7) * 32u + loffb;
                uint32_t bh[8];
#pragma unroll
                for (int tp = 0; tp < 2; ++tp)
                    ldmx4(bh[tp * 4], bh[tp * 4 + 1], bh[tp * 4 + 2], bh[tp * 4 + 3],
                          bh_base + (uint32_t)tp * 16u * SKB);
                const uint8_t* wk = wbase + ks * 1024 + lane * 16;
#pragma unroll
                for (int g = 0; g < 4; ++g) {
                    uint4 ahi = *reinterpret_cast<const uint4*>(wk + g * 16384);
                    uint4 alo = *reinterpret_cast<const uint4*>(wk + g * 16384 + 512);
#pragma unroll
                    for (int nt = 0; nt < 4; ++nt) {
                        mma16816(acc[g][nt], ahi, bh[nt * 2], bh[nt * 2 + 1]);
                        mma16816(acc[g][nt], alo, bh[nt * 2], bh[nt * 2 + 1]);
                    }
                }
            }
            __syncthreads();   // all reads of rec buffers done before writes

            // ---- pointwise ----
            float bI[2] = { bs[m0],       bs[m0 + 8] };
            float bF[2] = { bs[128 + m0], bs[128 + m0 + 8] };
            float bG[2] = { bs[256 + m0], bs[256 + m0 + 8] };
            float bO[2] = { bs[384 + m0], bs[384 + m0 + 8] };
            int storef = (L == 1 && t == T_STEPS - 1);
#pragma unroll
            for (int nt = 0; nt < 4; ++nt) {
#pragma unroll
                for (int mi = 0; mi < 2; ++mi) {
                    int h = m0 + mi * 8;
#pragma unroll
                    for (int e = 0; e < 2; ++e) {
                        int n = nhalf * 32 + nt * 8 + nb0 + e;
                        float pi = acc[0][nt][mi * 2 + e] + bI[mi];
                        float pf = acc[1][nt][mi * 2 + e] + bF[mi];
                        float pg = acc[2][nt][mi * 2 + e] + bG[mi];
                        float po = acc[3][nt][mi * 2 + e] + bO[mi];
                        float cp = cbuf[h * CSTRIDE + n];
                        float cn = sigf(pf) * cp + sigf(pi) * tanh_fast(pg);
                        cbuf[h * CSTRIDE + n] = cn;
                        float hv = sigf(po) * tanh_fast(cn);
                        *reinterpret_cast<__half*>(
                            smb + out_b + (uint32_t)n * SKB + (uint32_t)h * 2u) =
                            __float2half_rn(hv);
                        if (storef) scr[h * 65 + n] = hv;
                    }
                }
            }
            __syncthreads();
        }
    }

    // ================= tail: LN + dense head (fp32) =================
    if (tid < NB) {
        int b = tid;
        float s = 0.f, ss = 0.f;
        for (int h = 0; h < H; ++h) {
            float v = scr[h * 65 + b];
            s += v; ss += v * v;
        }
        float mu = s * (1.f / H);
        float rs = rsqrtf(ss * (1.f / H) - mu * mu + 1e-5f);
        for (int h = 0; h < H; ++h) {
            float v = scr[h * 65 + b];
            scr[h * 65 + b] = (v - mu) * rs * lnp[256 + h] + lnp[384 + h];
        }
    }
    __syncthreads();

    float* d1o = reinterpret_cast<float*>(smb);            // 32KB, act bufs dead
    float* d2o = reinterpret_cast<float*>(smb + OFF_H1);   // 16KB

    // dense1
    if (tid < 256) {
        int d4 = (tid >> 3) * 4, bb = (tid & 7) * 8;
        float a[4][8];
#pragma unroll
        for (int d = 0; d < 4; ++d)
#pragma unroll
            for (int b = 0; b < 8; ++b) a[d][b] = 0.f;
        for (int k = 0; k < H; ++k) {
            float4 wv = *reinterpret_cast<const float4*>(&g_Wd1t[k * 128 + d4]);
            float av[8];
#pragma unroll
            for (int b = 0; b < 8; ++b) av[b] = scr[k * 65 + bb + b];
#pragma unroll
            for (int b = 0; b < 8; ++b) {
                a[0][b] += wv.x * av[b]; a[1][b] += wv.y * av[b];
                a[2][b] += wv.z * av[b]; a[3][b] += wv.w * av[b];
            }
        }
#pragma unroll
        for (int d = 0; d < 4; ++d) {
            float bd = b_d1[d4 + d];
#pragma unroll
            for (int b = 0; b < 8; ++b) {
                float v = a[d][b] + bd;
                d1o[(d4 + d) * 64 + bb + b] = v > 0.f ? v : 0.f;
            }
        }
    }
    __syncthreads();

    // dense2
    if (tid < 256) {
        int d4 = (tid >> 4) * 4, bb = (tid & 15) * 4;
        float a[4][4];
#pragma unroll
        for (int d = 0; d < 4; ++d)
#pragma unroll
            for (int b = 0; b < 4; ++b) a[d][b] = 0.f;
        for (int k = 0; k < 128; ++k) {
            float4 wv = *reinterpret_cast<const float4*>(&g_Wd2t[k * 64 + d4]);
            float av[4];
#pragma unroll
            for (int b = 0; b < 4; ++b) av[b] = d1o[k * 64 + bb + b];
#pragma unroll
            for (int b = 0; b < 4; ++b) {
                a[0][b] += wv.x * av[b]; a[1][b] += wv.y * av[b];
                a[2][b] += wv.z * av[b]; a[3][b] += wv.w * av[b];
            }
        }
#pragma unroll
        for (int d = 0; d < 4; ++d) {
            float bd = b_d2[d4 + d];
#pragma unroll
            for (int b = 0; b < 4; ++b) {
                float v = a[d][b] + bd;
                d2o[(d4 + d) * 64 + bb + b] = v > 0.f ? v : 0.f;
            }
        }
    }
    __syncthreads();

    // dense3
    if (tid < 240) {
        int d = tid % 30, bq = (tid / 30) * 8;
        float a[8];
#pragma unroll
        for (int b = 0; b < 8; ++b) a[b] = 0.f;
        for (int k = 0; k < 64; ++k) {
            float wv = W_d3[d * 64 + k];
#pragma unroll
            for (int b = 0; b < 8; ++b) a[b] += wv * d2o[k * 64 + bq + b];
        }
        float bd = b_d3[d];
#pragma unroll
        for (int b = 0; b < 8; ++b)
            out[(long long)(bbase + bq + b) * 30 + d] = a[b] + bd;
    }
}

// ---------------------------------------------------------------------------
extern "C" void kernel_launch(void* const* d_in, const int* in_sizes, int n_in,
                              void* d_out, int out_size)
{
    const float* x     = (const float*)d_in[0];
    const float* W_in  = (const float*)d_in[1];
    const float* b_in  = (const float*)d_in[2];
    const float* g_in  = (const float*)d_in[3];
    const float* be_in = (const float*)d_in[4];
    const float* Wih0  = (const float*)d_in[5];
    const float* Whh0  = (const float*)d_in[6];
    const float* bih0  = (const float*)d_in[7];
    const float* bhh0  = (const float*)d_in[8];
    const float* Wih1  = (const float*)d_in[9];
    const float* Whh1  = (const float*)d_in[10];
    const float* bih1  = (const float*)d_in[11];
    const float* bhh1  = (const float*)d_in[12];
    const float* g_ln  = (const float*)d_in[13];
    const float* be_ln = (const float*)d_in[14];
    const float* W_d1  = (const float*)d_in[15];
    const float* b_d1  = (const float*)d_in[16];
    const float* W_d2  = (const float*)d_in[17];
    const float* b_d2  = (const float*)d_in[18];
    const float* W_d3  = (const float*)d_in[19];
    const float* b_d3  = (const float*)d_in[20];
    float* out = (float*)d_out;

    prep_kernel<<<128, 256>>>(Wih0, Whh0, bih0, bhh0, Wih1, Whh1, bih1, bhh1,
                              W_d1, W_d2);

    cudaFuncSetAttribute(lstm_hmma_kernel,
                         cudaFuncAttributeMaxDynamicSharedMemorySize,
                         (int)SMEM_TOTAL);
    lstm_hmma_kernel<<<NCTA, NTHR, SMEM_TOTAL>>>(x, W_in, b_in, g_in, be_in,
                                                 g_ln, be_ln, b_d1, b_d2,
                                                 W_d3, b_d3, out);
}

// round 13
// speedup vs baseline: 1.3427x; 1.3427x over previous
#include <cuda_runtime.h>
#include <cuda_fp16.h>
#include <cstdint>

#define B_TOT 8192
#define T_STEPS 90
#define H 128
#define NB 64
#define NCTA 128
#define NTHR 512
#define SKB 272u          // act row stride bytes (128 fp16 + 8 pad)

// ---- SMEM byte offsets ----
#define OFF_XA     0u         // [64][136] fp16
#define OFF_H0     17408u
#define OFF_H1     34816u
#define OFF_WBUF   52224u     // 16 warps x 2 stages x 4096B = 131072
#define OFF_LNPART 183296u    // [64][8][2] f32 = 4096
#define OFF_MURS   187392u    // [64][2] f32 = 512
#define OFF_WIN    187904u    // [128][8] f32 (slot7 = b_in)
#define OFF_LNP    192000u    // g_in,be_in,g_ln,be_ln (4x128 f32)
#define OFF_B0     194048u
#define OFF_B1     196096u
#define SMEM_TOTAL 198144u
// tail overlays (wbuf dead): scr f32 [128][65] @OFF_WBUF, d1o @+33280, d2o @+66048

// ---- device globals ----
// fp16 hi/lo fragments, stream order: [L][ks][wq][g][hl][32 lanes x 16B]
__device__ __align__(256) uint8_t g_Wpack[1048576];
__device__ float g_Wd1t[128 * 128];
__device__ float g_Wd2t[128 * 64];
__device__ float g_bias0[512];
__device__ float g_bias1[512];

__global__ void prep_kernel(const float* __restrict__ Wih0, const float* __restrict__ Whh0,
                            const float* __restrict__ bih0, const float* __restrict__ bhh0,
                            const float* __restrict__ Wih1, const float* __restrict__ Whh1,
                            const float* __restrict__ bih1, const float* __restrict__ bhh1,
                            const float* __restrict__ Wd1,  const float* __restrict__ Wd2)
{
    int idx = blockIdx.x * blockDim.x + threadIdx.x;
    int stride = gridDim.x * blockDim.x;
    for (int i = idx; i < 524288; i += stride) {
        int e    = i & 1;
        int reg  = (i >> 1) & 3;
        int lane = (i >> 3) & 31;
        int hl   = (i >> 8) & 1;
        int g    = (i >> 9) & 3;
        int wq   = (i >> 11) & 7;
        int ks   = (i >> 14) & 15;
        int L    = (i >> 18) & 1;
        int j = g * 128 + wq * 16 + (lane >> 2) + (reg & 1) * 8;
        int k = ks * 16 + (lane & 3) * 2 + ((reg >> 1) & 1) * 8 + e;
        float v;
        if (L == 0) v = (k < H) ? Wih0[j * H + k] : Whh0[j * H + (k - H)];
        else        v = (k < H) ? Wih1[j * H + k] : Whh1[j * H + (k - H)];
        __half hi = __float2half_rn(v);
        __half lo = __float2half_rn(v - __half2float(hi));
        reinterpret_cast<__half*>(g_Wpack)[i] = hl ? lo : hi;
    }
    for (int i = idx; i < 128 * 128; i += stride) {
        int k = i >> 7, d = i & 127;
        g_Wd1t[i] = Wd1[d * H + k];
    }
    for (int i = idx; i < 128 * 64; i += stride) {
        int k = i >> 6, d = i & 63;
        g_Wd2t[i] = Wd2[d * 128 + k];
    }
    for (int i = idx; i < 512; i += stride) {
        g_bias0[i] = bih0[i] + bhh0[i];
        g_bias1[i] = bih1[i] + bhh1[i];
    }
}

// ---- helpers ----
__device__ __forceinline__ uint32_t smem_u32_of(const void* p) {
    uint32_t a;
    asm("{ .reg .u64 t; cvta.to.shared.u64 t, %1; cvt.u32.u64 %0, t; }" : "=r"(a) : "l"(p));
    return a;
}
__device__ __forceinline__ void cp16(uint32_t dst, const void* src) {
    asm volatile("cp.async.ca.shared.global [%0], [%1], 16;" :: "r"(dst), "l"(src));
}
__device__ __forceinline__ void cp_commit() {
    asm volatile("cp.async.commit_group;" ::: "memory");
}
template <int N>
__device__ __forceinline__ void cp_wait() {
    asm volatile("cp.async.wait_group %0;" :: "n"(N) : "memory");
}
__device__ __forceinline__ uint4 lds128(uint32_t addr) {
    uint4 r;
    asm volatile("ld.shared.v4.b32 {%0,%1,%2,%3}, [%4];"
                 : "=r"(r.x), "=r"(r.y), "=r"(r.z), "=r"(r.w) : "r"(addr));
    return r;
}
__device__ __forceinline__ void ldmx4(uint32_t& r0, uint32_t& r1, uint32_t& r2, uint32_t& r3,
                                      uint32_t addr) {
    asm volatile("ldmatrix.sync.aligned.m8n8.x4.shared.b16 {%0,%1,%2,%3}, [%4];"
                 : "=r"(r0), "=r"(r1), "=r"(r2), "=r"(r3) : "r"(addr));
}
__device__ __forceinline__ void mma16816(float* c, uint4 a, uint32_t b0, uint32_t b1) {
    asm volatile("mma.sync.aligned.m16n8k16.row.col.f32.f16.f16.f32 "
                 "{%0,%1,%2,%3}, {%4,%5,%6,%7}, {%8,%9}, {%0,%1,%2,%3};"
                 : "+f"(c[0]), "+f"(c[1]), "+f"(c[2]), "+f"(c[3])
                 : "r"(a.x), "r"(a.y), "r"(a.z), "r"(a.w), "r"(b0), "r"(b1));
}
__device__ __forceinline__ float sigf(float x) {
    return __fdividef(1.f, 1.f + __expf(-x));
}
__device__ __forceinline__ float tanh_fast(float x) {
    return 2.f * sigf(2.f * x) - 1.f;
}

__global__ void __launch_bounds__(NTHR, 1)
lstm_hmma_kernel(const float* __restrict__ x,
                 const float* __restrict__ W_in, const float* __restrict__ b_in,
                 const float* __restrict__ g_in, const float* __restrict__ be_in,
                 const float* __restrict__ g_ln, const float* __restrict__ be_ln,
                 const float* __restrict__ b_d1, const float* __restrict__ b_d2,
                 const float* __restrict__ W_d3, const float* __restrict__ b_d3,
                 float* __restrict__ out)
{
    extern __shared__ __align__(256) uint8_t smb[];
    const int tid   = threadIdx.x;
    const int w     = tid >> 5;
    const int wq    = w & 7;           // h-row group
    const int nhalf = w >> 3;          // n half
    const int lane  = tid & 31;
    const int bbase = blockIdx.x * NB;

    uint32_t smbase = smem_u32_of(smb);
    float* lnpart = reinterpret_cast<float*>(smb + OFF_LNPART);
    float* murs   = reinterpret_cast<float*>(smb + OFF_MURS);
    float* wins   = reinterpret_cast<float*>(smb + OFF_WIN);
    float* lnp    = reinterpret_cast<float*>(smb + OFF_LNP);
    float* b0s    = reinterpret_cast<float*>(smb + OFF_B0);
    float* b1s    = reinterpret_cast<float*>(smb + OFF_B1);

    // ---- prologue ----
    for (int i = tid; i < (3 * 17408) / 4; i += NTHR)
        reinterpret_cast<uint32_t*>(smb + OFF_XA)[i] = 0u;       // act buffers
    for (int i = tid; i < H * 7; i += NTHR) {
        int h = i / 7, f = i % 7;
        wins[h * 8 + f] = W_in[i];
    }
    for (int i = tid; i < H; i += NTHR) {
        wins[i * 8 + 7] = b_in[i];
        lnp[i] = g_in[i]; lnp[128 + i] = be_in[i];
        lnp[256 + i] = g_ln[i]; lnp[384 + i] = be_ln[i];
    }
    for (int i = tid; i < 512; i += NTHR) { b0s[i] = g_bias0[i]; b1s[i] = g_bias1[i]; }
    __syncthreads();

    // ldmatrix lane offset (acts), includes nhalf offset
    const int tI = lane >> 3, r = lane & 7;
    const uint32_t loffb = (uint32_t)((tI >> 1) * 8 + r) * SKB + (uint32_t)(tI & 1) * 16u
                         + (uint32_t)nhalf * 32u * SKB;

    const int m0  = wq * 16 + (lane >> 2);
    const int nb0 = (lane & 3) * 2;

    // per-lane weight staging base (own 16B per q-block)
    const uint32_t wb_lane = smbase + OFF_WBUF + (uint32_t)w * 8192u + (uint32_t)lane * 16u;

    // cell state in registers: idx = nt*4 + mi*2 + e
    float c0r[16], c1r[16];
#pragma unroll
    for (int i = 0; i < 16; ++i) { c0r[i] = 0.f; c1r[i] = 0.f; }

    for (int t = 0; t < T_STEPS; ++t) {
        // ========= phase A: per-thread rows: proj -> LN -> fp16 xa =========
        {
            int b = tid >> 3, sub = tid & 7;
            const float* xr = x + ((long long)(bbase + b) * T_STEPS + t) * 7;
            float xv[7];
#pragma unroll
            for (int f = 0; f < 7; ++f) xv[f] = xr[f];
            float pr[16];
            float s = 0.f, ss = 0.f;
#pragma unroll
            for (int hh = 0; hh < 16; ++hh) {
                int h = sub * 16 + hh;
                float p = wins[h * 8 + 7];
#pragma unroll
                for (int f = 0; f < 7; ++f) p += wins[h * 8 + f] * xv[f];
                pr[hh] = p; s += p; ss += p * p;
            }
            lnpart[(b * 8 + sub) * 2]     = s;
            lnpart[(b * 8 + sub) * 2 + 1] = ss;
            __syncthreads();
            if (tid < NB) {
                float sr = 0.f, ssr = 0.f;
#pragma unroll
                for (int q = 0; q < 8; ++q) {
                    sr  += lnpart[(tid * 8 + q) * 2];
                    ssr += lnpart[(tid * 8 + q) * 2 + 1];
                }
                float mu = sr * (1.f / H);
                float rs = rsqrtf(ssr * (1.f / H) - mu * mu + 1e-5f);
                murs[tid * 2] = mu; murs[tid * 2 + 1] = rs;
            }
            __syncthreads();
            float mu = murs[b * 2], rs = murs[b * 2 + 1];
            uint32_t dst = smbase + OFF_XA + (uint32_t)b * SKB + (uint32_t)(sub * 16) * 2u;
#pragma unroll
            for (int hh = 0; hh < 16; hh += 2) {
                int h = sub * 16 + hh;
                float v0 = (pr[hh]     - mu) * rs * lnp[h]     + lnp[128 + h];
                float v1 = (pr[hh + 1] - mu) * rs * lnp[h + 1] + lnp[128 + h + 1];
                __half2 pk = __floats2half2_rn(v0, v1);
                asm volatile("st.shared.b32 [%0], %1;" :: "r"(dst + hh * 2u),
                             "r"(*reinterpret_cast<uint32_t*>(&pk)) : "memory");
            }
            __syncthreads();
        }

        // ========= two LSTM layers =========
#pragma unroll 1
        for (int L = 0; L < 2; ++L) {
            uint32_t in_b  = smbase + (L == 0 ? OFF_XA : OFF_H0);
            uint32_t re_b  = smbase + (L == 0 ? OFF_H0 : OFF_H1);
            uint32_t out_b = (L == 0 ? OFF_H0 : OFF_H1);
            const float* bs = (L == 0) ? b0s : b1s;
            float* creg = (L == 0) ? c0r : c1r;
            const uint8_t* wsrc0 = g_Wpack + ((size_t)(L * 16) * 8 + wq) * 4096 + lane * 16;

            // prefetch stages 0,1 (ks 0,1)
#pragma unroll
            for (int p = 0; p < 2; ++p) {
                const uint8_t* src = wsrc0 + (size_t)p * 8 * 4096;
                uint32_t dst = wb_lane + (uint32_t)p * 4096u;
#pragma unroll
                for (int q = 0; q < 8; ++q) cp16(dst + q * 512u, src + q * 512);
                cp_commit();
            }

            float acc[4][4][4];
#pragma unroll
            for (int g = 0; g < 4; ++g)
#pragma unroll
                for (int nt = 0; nt < 4; ++nt)
#pragma unroll
                    for (int q = 0; q < 4; ++q) acc[g][nt][q] = 0.f;

#pragma unroll 2
            for (int ks = 0; ks < 16; ++ks) {
                if (ks == 15) cp_wait<0>(); else cp_wait<1>();

                uint32_t bh_base = ((ks < 8) ? in_b : re_b) + (uint32_t)(ks & 7) * 32u + loffb;
                uint32_t bh[8];
#pragma unroll
                for (int tp = 0; tp < 2; ++tp)
                    ldmx4(bh[tp * 4], bh[tp * 4 + 1], bh[tp * 4 + 2], bh[tp * 4 + 3],
                          bh_base + (uint32_t)tp * 16u * SKB);

                uint32_t wsm = wb_lane + (uint32_t)(ks & 1) * 4096u;
#pragma unroll
                for (int g = 0; g < 4; ++g) {
                    uint4 ahi = lds128(wsm + (uint32_t)(g * 2) * 512u);
                    uint4 alo = lds128(wsm + (uint32_t)(g * 2 + 1) * 512u);
#pragma unroll
                    for (int nt = 0; nt < 4; ++nt) {
                        mma16816(acc[g][nt], ahi, bh[nt * 2], bh[nt * 2 + 1]);
                        mma16816(acc[g][nt], alo, bh[nt * 2], bh[nt * 2 + 1]);
                    }
                }

                if (ks < 14) {
                    const uint8_t* src = wsrc0 + (size_t)(ks + 2) * 8 * 4096;
                    uint32_t dst = wb_lane + (uint32_t)(ks & 1) * 4096u;
#pragma unroll
                    for (int q = 0; q < 8; ++q) cp16(dst + q * 512u, src + q * 512);
                    cp_commit();
                }
            }
            __syncthreads();   // all reads of rec buffers done before writes

            // ---- pointwise (c in registers) ----
            float bI[2] = { bs[m0],       bs[m0 + 8] };
            float bF[2] = { bs[128 + m0], bs[128 + m0 + 8] };
            float bG[2] = { bs[256 + m0], bs[256 + m0 + 8] };
            float bO[2] = { bs[384 + m0], bs[384 + m0 + 8] };
            int storef = (L == 1 && t == T_STEPS - 1);
            float* scrT = reinterpret_cast<float*>(smb + OFF_WBUF);
#pragma unroll
            for (int nt = 0; nt < 4; ++nt) {
#pragma unroll
                for (int mi = 0; mi < 2; ++mi) {
                    int h = m0 + mi * 8;
#pragma unroll
                    for (int e = 0; e < 2; ++e) {
                        int idx = nt * 4 + mi * 2 + e;
                        int n = nhalf * 32 + nt * 8 + nb0 + e;
                        float pi = acc[0][nt][mi * 2 + e] + bI[mi];
                        float pf = acc[1][nt][mi * 2 + e] + bF[mi];
                        float pg = acc[2][nt][mi * 2 + e] + bG[mi];
                        float po = acc[3][nt][mi * 2 + e] + bO[mi];
                        float cn = sigf(pf) * creg[idx] + sigf(pi) * tanh_fast(pg);
                        creg[idx] = cn;
                        float hv = sigf(po) * tanh_fast(cn);
                        *reinterpret_cast<__half*>(
                            smb + out_b + (uint32_t)n * SKB + (uint32_t)h * 2u) =
                            __float2half_rn(hv);
                        if (storef) scrT[h * 65 + n] = hv;
                    }
                }
            }
            __syncthreads();
        }
    }

    // ================= tail: LN + dense head (fp32); wbuf dead =================
    float* scr = reinterpret_cast<float*>(smb + OFF_WBUF);          // [128][65]
    float* d1o = reinterpret_cast<float*>(smb + OFF_WBUF + 33280u); // [128][64]
    float* d2o = reinterpret_cast<float*>(smb + OFF_WBUF + 66048u); // [64][64]

    if (tid < NB) {
        int b = tid;
        float s = 0.f, ss = 0.f;
        for (int h = 0; h < H; ++h) {
            float v = scr[h * 65 + b];
            s += v; ss += v * v;
        }
        float mu = s * (1.f / H);
        float rs = rsqrtf(ss * (1.f / H) - mu * mu + 1e-5f);
        for (int h = 0; h < H; ++h) {
            float v = scr[h * 65 + b];
            scr[h * 65 + b] = (v - mu) * rs * lnp[256 + h] + lnp[384 + h];
        }
    }
    __syncthreads();

    // dense1
    if (tid < 256) {
        int d4 = (tid >> 3) * 4, bb = (tid & 7) * 8;
        float a[4][8];
#pragma unroll
        for (int d = 0; d < 4; ++d)
#pragma unroll
            for (int b = 0; b < 8; ++b) a[d][b] = 0.f;
        for (int k = 0; k < H; ++k) {
            float4 wv = *reinterpret_cast<const float4*>(&g_Wd1t[k * 128 + d4]);
            float av[8];
#pragma unroll
            for (int b = 0; b < 8; ++b) av[b] = scr[k * 65 + bb + b];
#pragma unroll
            for (int b = 0; b < 8; ++b) {
                a[0][b] += wv.x * av[b]; a[1][b] += wv.y * av[b];
                a[2][b] += wv.z * av[b]; a[3][b] += wv.w * av[b];
            }
        }
#pragma unroll
        for (int d = 0; d < 4; ++d) {
            float bd = b_d1[d4 + d];
#pragma unroll
            for (int b = 0; b < 8; ++b) {
                float v = a[d][b] + bd;
                d1o[(d4 + d) * 64 + bb + b] = v > 0.f ? v : 0.f;
            }
        }
    }
    __syncthreads();

    // dense2
    if (tid < 256) {
        int d4 = (tid >> 4) * 4, bb = (tid & 15) * 4;
        float a[4][4];
#pragma unroll
        for (int d = 0; d < 4; ++d)
#pragma unroll
            for (int b = 0; b < 4; ++b) a[d][b] = 0.f;
        for (int k = 0; k < 128; ++k) {
            float4 wv = *reinterpret_cast<const float4*>(&g_Wd2t[k * 64 + d4]);
            float av[4];
#pragma unroll
            for (int b = 0; b < 4; ++b) av[b] = d1o[k * 64 + bb + b];
#pragma unroll
            for (int b = 0; b < 4; ++b) {
                a[0][b] += wv.x * av[b]; a[1][b] += wv.y * av[b];
                a[2][b] += wv.z * av[b]; a[3][b] += wv.w * av[b];
            }
        }
#pragma unroll
        for (int d = 0; d < 4; ++d) {
            float bd = b_d2[d4 + d];
#pragma unroll
            for (int b = 0; b < 4; ++b) {
                float v = a[d][b] + bd;
                d2o[(d4 + d) * 64 + bb + b] = v > 0.f ? v : 0.f;
            }
        }
    }
    __syncthreads();

    // dense3
    if (tid < 240) {
        int d = tid % 30, bq = (tid / 30) * 8;
        float a[8];
#pragma unroll
        for (int b = 0; b < 8; ++b) a[b] = 0.f;
        for (int k = 0; k < 64; ++k) {
            float wv = W_d3[d * 64 + k];
#pragma unroll
            for (int b = 0; b < 8; ++b) a[b] += wv * d2o[k * 64 + bq + b];
        }
        float bd = b_d3[d];
#pragma unroll
        for (int b = 0; b < 8; ++b)
            out[(long long)(bbase + bq + b) * 30 + d] = a[b] + bd;
    }
}

// ---------------------------------------------------------------------------
extern "C" void kernel_launch(void* const* d_in, const int* in_sizes, int n_in,
                              void* d_out, int out_size)
{
    const float* x     = (const float*)d_in[0];
    const float* W_in  = (const float*)d_in[1];
    const float* b_in  = (const float*)d_in[2];
    const float* g_in  = (const float*)d_in[3];
    const float* be_in = (const float*)d_in[4];
    const float* Wih0  = (const float*)d_in[5];
    const float* Whh0  = (const float*)d_in[6];
    const float* bih0  = (const float*)d_in[7];
    const float* bhh0  = (const float*)d_in[8];
    const float* Wih1  = (const float*)d_in[9];
    const float* Whh1  = (const float*)d_in[10];
    const float* bih1  = (const float*)d_in[11];
    const float* bhh1  = (const float*)d_in[12];
    const float* g_ln  = (const float*)d_in[13];
    const float* be_ln = (const float*)d_in[14];
    const float* W_d1  = (const float*)d_in[15];
    const float* b_d1  = (const float*)d_in[16];
    const float* W_d2  = (const float*)d_in[17];
    const float* b_d2  = (const float*)d_in[18];
    const float* W_d3  = (const float*)d_in[19];
    const float* b_d3  = (const float*)d_in[20];
    float* out = (float*)d_out;

    prep_kernel<<<128, 256>>>(Wih0, Whh0, bih0, bhh0, Wih1, Whh1, bih1, bhh1,
                              W_d1, W_d2);

    cudaFuncSetAttribute(lstm_hmma_kernel,
                         cudaFuncAttributeMaxDynamicSharedMemorySize,
                         (int)SMEM_TOTAL);
    lstm_hmma_kernel<<<NCTA, NTHR, SMEM_TOTAL>>>(x, W_in, b_in, g_in, be_in,
                                                 g_ln, be_ln, b_d1, b_d2,
                                                 W_d3, b_d3, out);
}